// round 7
// baseline (speedup 1.0000x reference)
#include <cuda_runtime.h>
#include <cuda_fp16.h>
#include <math.h>
#include <stdint.h>

#define NTOK 2048
#define CDIM 1024
#define IDIM 4096
#define NEXP 8
#define HR   256

#define BM 128
#define BN 128
#define BK 32
#define THREADS 256   // 8 warps, 64x32 warp tiles

// smem (half units): A stage 128x40, B stage 32x136, 3 stages
#define A_ST 40
#define B_ST 136
#define ABUF 5120               // halves per A stage
#define BBUF 4352               // halves per B stage
#define B_BASE (3 * ABUF)       // 15360
#define SMEM_BYTES ((3 * (ABUF + BBUF)) * 2)   // 56832

// ---------------- scratch ----------------------------------------------------
__device__ int    g_count[NEXP];
__device__ int    g_cursor[NEXP];
__device__ int    g_base[NEXP];
__device__ int    g_row_tok[NTOK * 2];
__device__ int    g_row_of[NTOK * 2];
__device__ int    g_tok_eidx[NTOK * 2];
__device__ float  g_tok_w[NTOK * 2];
__device__ __half g_xh[(size_t)NTOK * CDIM];
__device__ __half g_ew1h[(size_t)NEXP * CDIM * IDIM];
__device__ __half g_ew2h[(size_t)NEXP * IDIM * CDIM];
__device__ __half g_sw1h[(size_t)CDIM * IDIM];
__device__ __half g_sw2h[(size_t)IDIM * CDIM];
__device__ __half g_hbufh[(size_t)NTOK * 2 * IDIM];
__device__ __half g_hsh[(size_t)NTOK * IDIM];
__device__ float  g_ybuf[(size_t)NTOK * 2 * CDIM];

// ---------------- helpers ----------------------------------------------------
__device__ __forceinline__ uint32_t smem_u32(const void* p) {
    uint32_t a;
    asm("{ .reg .u64 t; cvta.to.shared.u64 t, %1; cvt.u32.u64 %0, t; }" : "=r"(a) : "l"(p));
    return a;
}
__device__ __forceinline__ void cp16(uint32_t dst, const void* src) {
    asm volatile("cp.async.cg.shared.global [%0], [%1], 16;" :: "r"(dst), "l"(src) : "memory");
}
__device__ __forceinline__ void cp_commit() {
    asm volatile("cp.async.commit_group;" ::: "memory");
}
template<int N> __device__ __forceinline__ void cp_wait() {
    asm volatile("cp.async.wait_group %0;" :: "n"(N) : "memory");
}
__device__ __forceinline__ void mma16(float* c, const uint32_t* a, const uint32_t* b) {
    asm volatile(
        "mma.sync.aligned.m16n8k16.row.col.f32.f16.f16.f32 "
        "{%0,%1,%2,%3}, {%4,%5,%6,%7}, {%8,%9}, {%0,%1,%2,%3};"
        : "+f"(c[0]), "+f"(c[1]), "+f"(c[2]), "+f"(c[3])
        : "r"(a[0]), "r"(a[1]), "r"(a[2]), "r"(a[3]), "r"(b[0]), "r"(b[1]));
}
__device__ __forceinline__ void ldsm4(uint32_t* r, uint32_t addr) {
    asm volatile("ldmatrix.sync.aligned.m8n8.x4.shared.b16 {%0,%1,%2,%3}, [%4];"
        : "=r"(r[0]), "=r"(r[1]), "=r"(r[2]), "=r"(r[3]) : "r"(addr));
}
__device__ __forceinline__ void ldsm4t(uint32_t* r, uint32_t addr) {
    asm volatile("ldmatrix.sync.aligned.m8n8.x4.trans.shared.b16 {%0,%1,%2,%3}, [%4];"
        : "=r"(r[0]), "=r"(r[1]), "=r"(r[2]), "=r"(r[3]) : "r"(addr));
}
__device__ __forceinline__ uint32_t pkh2(float a, float b) {
    __half2 h = __floats2half2_rn(a, b);
    return *(uint32_t*)&h;
}

// ---------------- init -------------------------------------------------------
__global__ void init_k() {
    int t = threadIdx.x;
    if (t < NEXP) { g_count[t] = 0; g_cursor[t] = 0; }
}

// ---------------- router: 8 tokens per block, exact fp32 ---------------------
__global__ void router_k(const float* __restrict__ x,
                         const float* __restrict__ rw1, const float* __restrict__ rb1,
                         const float* __restrict__ rw2, const float* __restrict__ rb2) {
    __shared__ float xs[8][CDIM];
    __shared__ float hs[8][HR];
    int t = threadIdx.x;
    int tok0 = blockIdx.x * 8;
    {
        const float4* xr = (const float4*)(x + (size_t)tok0 * CDIM);
        float4* xd = (float4*)&xs[0][0];
        for (int i = t; i < 8 * CDIM / 4; i += 256) xd[i] = xr[i];
    }
    __syncthreads();
    float acc[8];
    float b = rb1[t];
    #pragma unroll
    for (int k = 0; k < 8; k++) acc[k] = b;
    #pragma unroll 4
    for (int c = 0; c < CDIM; c++) {
        float w = rw1[(size_t)c * HR + t];
        #pragma unroll
        for (int k = 0; k < 8; k++) acc[k] += xs[k][c] * w;
    }
    #pragma unroll
    for (int k = 0; k < 8; k++) hs[k][t] = fmaxf(acc[k], 0.0f);
    __syncthreads();
    int w = t >> 5, l = t & 31;
    float lg = 0.0f;
    if (l < NEXP) {
        lg = rb2[l];
        for (int h = 0; h < HR; h++) lg += hs[w][h] * rw2[(size_t)h * NEXP + l];
    }
    float lgs[NEXP];
    #pragma unroll
    for (int e = 0; e < NEXP; e++) lgs[e] = __shfl_sync(0xffffffffu, lg, e);
    if (l == 0) {
        int n = tok0 + w;
        float mx = lgs[0];
        for (int e = 1; e < NEXP; e++) mx = fmaxf(mx, lgs[e]);
        float ge[NEXP]; float s = 0.0f;
        for (int e = 0; e < NEXP; e++) { ge[e] = expf(lgs[e] - mx); s += ge[e]; }
        for (int e = 0; e < NEXP; e++) ge[e] /= s;
        int i0 = 0;
        for (int e = 1; e < NEXP; e++) if (ge[e] > ge[i0]) i0 = e;
        int i1 = -1;
        for (int e = 0; e < NEXP; e++) {
            if (e == i0) continue;
            if (i1 < 0 || ge[e] > ge[i1]) i1 = e;
        }
        float a = expf(ge[i0] * 0.5f), c = expf(ge[i1] * 0.5f);
        float inv = 1.0f / (a + c);
        g_tok_eidx[n * 2] = i0;  g_tok_eidx[n * 2 + 1] = i1;
        g_tok_w[n * 2] = a * inv;
        g_tok_w[n * 2 + 1] = c * inv;
        atomicAdd(&g_count[i0], 1);
        atomicAdd(&g_count[i1], 1);
    }
}

__global__ void scan_k() {
    if (threadIdx.x == 0) {
        int s = 0;
        for (int e = 0; e < NEXP; e++) { g_base[e] = s; s += g_count[e]; }
    }
}

__global__ void fill_k() {
    int n = blockIdx.x * blockDim.x + threadIdx.x;
    if (n >= NTOK) return;
    #pragma unroll
    for (int k = 0; k < 2; k++) {
        int e = g_tok_eidx[n * 2 + k];
        int slot = atomicAdd(&g_cursor[e], 1);
        int row = g_base[e] + slot;
        g_row_tok[row] = n;
        g_row_of[n * 2 + k] = row;
    }
}

// ---------------- fp32 -> fp16 conversion ------------------------------------
__global__ void f2h_k(const float4* __restrict__ in, uint4* __restrict__ out, int n8) {
    int i = blockIdx.x * blockDim.x + threadIdx.x;
    if (i >= n8) return;
    float4 v0 = in[2 * i], v1 = in[2 * i + 1];
    uint4 o;
    o.x = pkh2(v0.x, v0.y);
    o.y = pkh2(v0.z, v0.w);
    o.z = pkh2(v1.x, v1.y);
    o.w = pkh2(v1.z, v1.w);
    out[i] = o;
}

// ---------------- fp16 mma.sync GEMM, 8 warps, 64x32 warp tiles --------------
template<bool EXPERT, bool GATHER, bool SILU>
__global__ void __launch_bounds__(THREADS, 2) tgemm_k(
    const __half* __restrict__ A, const __half* __restrict__ Bw,
    const float* __restrict__ bias, void* __restrict__ Cm,
    int M, int K, int Nd)
{
    extern __shared__ __half sm[];
    int rowbase = 0;
    if (EXPERT) {
        int e = blockIdx.z;
        M = g_count[e];
        rowbase = g_base[e];
        Bw   += (size_t)e * K * Nd;
        bias += (size_t)e * Nd;
    }
    int m0 = blockIdx.y * BM;
    if (m0 >= M) return;
    int n0 = blockIdx.x * BN;
    int t = threadIdx.x;
    int wid = t >> 5, lane = t & 31;
    int g = lane >> 2, tig = lane & 3;
    int mw = (wid >> 2) * 64, nw = (wid & 3) * 32;
    uint32_t sbase = smem_u32(sm);

    // ---- A cp.async roles: 2 chunks/thread (rows 64 apart); row = 32h = 4x16B
    int ar = t >> 2, aq = t & 3;
    const __half* aptrs[2];
    uint32_t aoffs[2];
    #pragma unroll
    for (int i = 0; i < 2; i++) {
        int r = ar + 64 * i;
        int rr = m0 + r;
        int rc = rr < M ? rr : (M - 1);
        int src = GATHER ? g_row_tok[rowbase + rc] : (EXPERT ? (rowbase + rc) : rc);
        aptrs[i] = A + (size_t)src * K + aq * 8;
        aoffs[i] = (uint32_t)((r * A_ST + aq * 8) * 2);
    }
    // ---- B cp.async roles: 2 chunks/thread (rows 16 apart); row = 128h = 16x16B
    int br = t >> 4, bq = t & 15;
    const __half* bptr = Bw + (size_t)br * Nd + n0 + bq * 8;
    uint32_t boff0 = (uint32_t)((br * B_ST + bq * 8) * 2);

    // ---- ldmatrix lane addresses (half units) ----
    uint32_t laneA = (uint32_t)((mw + (lane & 15)) * A_ST + (lane >> 4) * 8);
    uint32_t laneB = (uint32_t)((((lane >> 3) & 1) * 8 + (lane & 7)) * B_ST
                                + nw + ((lane >> 4) & 1) * 8);

    float c[4][4][4];
    #pragma unroll
    for (int mf = 0; mf < 4; mf++)
        #pragma unroll
        for (int nf = 0; nf < 4; nf++)
            #pragma unroll
            for (int i = 0; i < 4; i++) c[mf][nf][i] = 0.0f;

    int iters = K / BK;

    #pragma unroll
    for (int s = 0; s < 2; s++) {
        uint32_t ab = sbase + s * (ABUF * 2);
        uint32_t bb = sbase + (B_BASE + s * BBUF) * 2;
        int kof = s * BK;
        #pragma unroll
        for (int i = 0; i < 2; i++) cp16(ab + aoffs[i], aptrs[i] + kof);
        #pragma unroll
        for (int i = 0; i < 2; i++)
            cp16(bb + boff0 + i * (16 * B_ST * 2), bptr + (size_t)(kof + 16 * i) * Nd);
        cp_commit();
    }

    for (int it = 0; it < iters; it++) {
        cp_wait<1>();
        __syncthreads();
        if (it + 2 < iters) {
            int s = (it + 2) % 3;
            uint32_t ab = sbase + s * (ABUF * 2);
            uint32_t bb = sbase + (B_BASE + s * BBUF) * 2;
            int kof = (it + 2) * BK;
            #pragma unroll
            for (int i = 0; i < 2; i++) cp16(ab + aoffs[i], aptrs[i] + kof);
            #pragma unroll
            for (int i = 0; i < 2; i++)
                cp16(bb + boff0 + i * (16 * B_ST * 2), bptr + (size_t)(kof + 16 * i) * Nd);
        }
        cp_commit();

        uint32_t Ab = sbase + (it % 3) * (ABUF * 2);
        uint32_t Bb = sbase + (B_BASE + (it % 3) * BBUF) * 2;
        #pragma unroll
        for (int ks = 0; ks < 2; ks++) {
            uint32_t a[4][4], b[4][2];
            #pragma unroll
            for (int mf = 0; mf < 4; mf++)
                ldsm4(a[mf], Ab + (laneA + mf * 16 * A_ST + ks * 16) * 2);
            #pragma unroll
            for (int np = 0; np < 2; np++) {
                uint32_t r[4];
                ldsm4t(r, Bb + (laneB + ks * 16 * B_ST + np * 16) * 2);
                b[2 * np][0] = r[0]; b[2 * np][1] = r[1];
                b[2 * np + 1][0] = r[2]; b[2 * np + 1][1] = r[3];
            }
            #pragma unroll
            for (int mf = 0; mf < 4; mf++)
                #pragma unroll
                for (int nf = 0; nf < 4; nf++)
                    mma16(c[mf][nf], a[mf], b[nf]);
        }
        // no trailing sync: next iter's top sync orders stage reuse
    }

    // ---- epilogue ----
    int outbase = EXPERT ? rowbase : 0;
    float2 bv[4];
    #pragma unroll
    for (int nf = 0; nf < 4; nf++)
        bv[nf] = *(const float2*)(bias + n0 + nw + nf * 8 + 2 * tig);
    #pragma unroll
    for (int mf = 0; mf < 4; mf++) {
        int row0 = m0 + mw + mf * 16 + g;
        #pragma unroll
        for (int nf = 0; nf < 4; nf++) {
            int col = n0 + nw + nf * 8 + 2 * tig;
            float v0 = c[mf][nf][0] + bv[nf].x, v1 = c[mf][nf][1] + bv[nf].y;
            float v2 = c[mf][nf][2] + bv[nf].x, v3 = c[mf][nf][3] + bv[nf].y;
            if (SILU) {
                v0 = v0 / (1.0f + __expf(-v0));
                v1 = v1 / (1.0f + __expf(-v1));
                v2 = v2 / (1.0f + __expf(-v2));
                v3 = v3 / (1.0f + __expf(-v3));
                __half* Ch = (__half*)Cm;
                if (row0 < M)
                    *(uint32_t*)(Ch + (size_t)(outbase + row0) * Nd + col) = pkh2(v0, v1);
                if (row0 + 8 < M)
                    *(uint32_t*)(Ch + (size_t)(outbase + row0 + 8) * Nd + col) = pkh2(v2, v3);
            } else {
                float* Cf = (float*)Cm;
                if (row0 < M)
                    *(float2*)(Cf + (size_t)(outbase + row0) * Nd + col) = make_float2(v0, v1);
                if (row0 + 8 < M)
                    *(float2*)(Cf + (size_t)(outbase + row0 + 8) * Nd + col) = make_float2(v2, v3);
            }
        }
    }
}

// ---------------- combine ----------------------------------------------------
__global__ void combine_k(const float* __restrict__ y, float* __restrict__ out) {
    int n = blockIdx.x;
    int r0 = g_row_of[n * 2], r1 = g_row_of[n * 2 + 1];
    float w0 = g_tok_w[n * 2], w1 = g_tok_w[n * 2 + 1];
    const float4* y0 = (const float4*)(y + (size_t)r0 * CDIM);
    const float4* y1 = (const float4*)(y + (size_t)r1 * CDIM);
    float4* o = (float4*)(out + (size_t)n * CDIM);
    for (int c = threadIdx.x; c < CDIM / 4; c += blockDim.x) {
        float4 a = y0[c], b = y1[c], v = o[c];
        v.x += w0 * a.x + w1 * b.x;
        v.y += w0 * a.y + w1 * b.y;
        v.z += w0 * a.z + w1 * b.z;
        v.w += w0 * a.w + w1 * b.w;
        o[c] = v;
    }
}

// ---------------- launch -----------------------------------------------------
extern "C" void kernel_launch(void* const* d_in, const int* in_sizes, int n_in,
                              void* d_out, int out_size) {
    const float* x   = (const float*)d_in[0];
    const float* rw1 = (const float*)d_in[1];
    const float* rb1 = (const float*)d_in[2];
    const float* rw2 = (const float*)d_in[3];
    const float* rb2 = (const float*)d_in[4];
    const float* ew1 = (const float*)d_in[5];
    const float* eb1 = (const float*)d_in[6];
    const float* ew2 = (const float*)d_in[7];
    const float* eb2 = (const float*)d_in[8];
    const float* sw1 = (const float*)d_in[9];
    const float* sb1 = (const float*)d_in[10];
    const float* sw2 = (const float*)d_in[11];
    const float* sb2 = (const float*)d_in[12];
    float* out = (float*)d_out;

    __half *xh, *ew1h, *ew2h, *sw1h, *sw2h, *hbufh, *hsh;
    float *ybuf;
    cudaGetSymbolAddress((void**)&xh,    g_xh);
    cudaGetSymbolAddress((void**)&ew1h,  g_ew1h);
    cudaGetSymbolAddress((void**)&ew2h,  g_ew2h);
    cudaGetSymbolAddress((void**)&sw1h,  g_sw1h);
    cudaGetSymbolAddress((void**)&sw2h,  g_sw2h);
    cudaGetSymbolAddress((void**)&hbufh, g_hbufh);
    cudaGetSymbolAddress((void**)&hsh,   g_hsh);
    cudaGetSymbolAddress((void**)&ybuf,  g_ybuf);

    cudaFuncSetAttribute(tgemm_k<false, false, true>,
                         cudaFuncAttributeMaxDynamicSharedMemorySize, SMEM_BYTES);
    cudaFuncSetAttribute(tgemm_k<false, false, false>,
                         cudaFuncAttributeMaxDynamicSharedMemorySize, SMEM_BYTES);
    cudaFuncSetAttribute(tgemm_k<true, true, true>,
                         cudaFuncAttributeMaxDynamicSharedMemorySize, SMEM_BYTES);
    cudaFuncSetAttribute(tgemm_k<true, false, false>,
                         cudaFuncAttributeMaxDynamicSharedMemorySize, SMEM_BYTES);

    init_k<<<1, 32>>>();
    router_k<<<NTOK / 8, 256>>>(x, rw1, rb1, rw2, rb2);
    scan_k<<<1, 32>>>();
    fill_k<<<(NTOK + 255) / 256, 256>>>();

    {
        auto cvt = [&](const float* in, __half* o, size_t n) {
            int n8 = (int)(n / 8);
            f2h_k<<<(n8 + 255) / 256, 256>>>((const float4*)in, (uint4*)o, n8);
        };
        cvt(x,   xh,   (size_t)NTOK * CDIM);
        cvt(ew1, ew1h, (size_t)NEXP * CDIM * IDIM);
        cvt(ew2, ew2h, (size_t)NEXP * IDIM * CDIM);
        cvt(sw1, sw1h, (size_t)CDIM * IDIM);
        cvt(sw2, sw2h, (size_t)IDIM * CDIM);
    }

    // routed experts
    tgemm_k<true, true, true><<<dim3(IDIM / BN, NTOK / BM, NEXP), THREADS, SMEM_BYTES>>>(
        xh, ew1h, eb1, hbufh, 0, CDIM, IDIM);
    tgemm_k<true, false, false><<<dim3(CDIM / BN, NTOK / BM, NEXP), THREADS, SMEM_BYTES>>>(
        hbufh, ew2h, eb2, ybuf, 0, IDIM, CDIM);

    // shared expert
    tgemm_k<false, false, true><<<dim3(IDIM / BN, NTOK / BM), THREADS, SMEM_BYTES>>>(
        xh, sw1h, sb1, hsh, NTOK, CDIM, IDIM);
    tgemm_k<false, false, false><<<dim3(CDIM / BN, NTOK / BM), THREADS, SMEM_BYTES>>>(
        hsh, sw2h, sb2, out, NTOK, IDIM, CDIM);

    combine_k<<<NTOK, 256>>>(ybuf, out);
}

// round 8
// speedup vs baseline: 1.2604x; 1.2604x over previous
#include <cuda_runtime.h>
#include <cuda_fp16.h>
#include <math.h>
#include <stdint.h>

#define NTOK 2048
#define CDIM 1024
#define IDIM 4096
#define NEXP 8
#define HR   256

#define BM 128
#define BN 128
#define BK 32
#define THREADS 128   // 4 warps, 64x64 warp tiles  (R6 best config)

// smem (half units): A stage 128x40, B stage 32x136, 3 stages
#define A_ST 40
#define B_ST 136
#define ABUF 5120
#define BBUF 4352
#define B_BASE (3 * ABUF)
#define SMEM_BYTES ((3 * (ABUF + BBUF)) * 2)   // 56832

// ---------------- scratch ----------------------------------------------------
__device__ int    g_count[NEXP];
__device__ int    g_cursor[NEXP];
__device__ int    g_base[NEXP];
__device__ int    g_row_tok[NTOK * 2];
__device__ int    g_row_of[NTOK * 2];
__device__ int    g_tok_eidx[NTOK * 2];
__device__ float  g_tok_w[NTOK * 2];
__device__ __half g_xh[(size_t)NTOK * CDIM];
__device__ __half g_ew1h[(size_t)NEXP * CDIM * IDIM];
__device__ __half g_ew2h[(size_t)NEXP * IDIM * CDIM];
__device__ __half g_sw1h[(size_t)CDIM * IDIM];
__device__ __half g_sw2h[(size_t)IDIM * CDIM];
__device__ __half g_hbufh[(size_t)NTOK * 2 * IDIM];
__device__ __half g_hsh[(size_t)NTOK * IDIM];
__device__ float  g_ybuf[(size_t)NTOK * 2 * CDIM];

// ---------------- helpers ----------------------------------------------------
__device__ __forceinline__ uint32_t smem_u32(const void* p) {
    uint32_t a;
    asm("{ .reg .u64 t; cvta.to.shared.u64 t, %1; cvt.u32.u64 %0, t; }" : "=r"(a) : "l"(p));
    return a;
}
__device__ __forceinline__ void cp16(uint32_t dst, const void* src) {
    asm volatile("cp.async.cg.shared.global [%0], [%1], 16;" :: "r"(dst), "l"(src) : "memory");
}
__device__ __forceinline__ void cp_commit() {
    asm volatile("cp.async.commit_group;" ::: "memory");
}
template<int N> __device__ __forceinline__ void cp_wait() {
    asm volatile("cp.async.wait_group %0;" :: "n"(N) : "memory");
}
__device__ __forceinline__ void mma16(float* c, const uint32_t* a, const uint32_t* b) {
    asm volatile(
        "mma.sync.aligned.m16n8k16.row.col.f32.f16.f16.f32 "
        "{%0,%1,%2,%3}, {%4,%5,%6,%7}, {%8,%9}, {%0,%1,%2,%3};"
        : "+f"(c[0]), "+f"(c[1]), "+f"(c[2]), "+f"(c[3])
        : "r"(a[0]), "r"(a[1]), "r"(a[2]), "r"(a[3]), "r"(b[0]), "r"(b[1]));
}
__device__ __forceinline__ void ldsm4(uint32_t* r, uint32_t addr) {
    asm volatile("ldmatrix.sync.aligned.m8n8.x4.shared.b16 {%0,%1,%2,%3}, [%4];"
        : "=r"(r[0]), "=r"(r[1]), "=r"(r[2]), "=r"(r[3]) : "r"(addr));
}
__device__ __forceinline__ void ldsm4t(uint32_t* r, uint32_t addr) {
    asm volatile("ldmatrix.sync.aligned.m8n8.x4.trans.shared.b16 {%0,%1,%2,%3}, [%4];"
        : "=r"(r[0]), "=r"(r[1]), "=r"(r[2]), "=r"(r[3]) : "r"(addr));
}
__device__ __forceinline__ uint32_t pkh2(float a, float b) {
    __half2 h = __floats2half2_rn(a, b);
    return *(uint32_t*)&h;
}

// ---------------- init -------------------------------------------------------
__global__ void init_k() {
    int t = threadIdx.x;
    if (t < NEXP) { g_count[t] = 0; g_cursor[t] = 0; }
}

// ---------------- router: 8 tokens per block, exact fp32 ---------------------
__global__ void router_k(const float* __restrict__ x,
                         const float* __restrict__ rw1, const float* __restrict__ rb1,
                         const float* __restrict__ rw2, const float* __restrict__ rb2) {
    __shared__ float xs[8][CDIM];
    __shared__ float hs[8][HR];
    int t = threadIdx.x;
    int tok0 = blockIdx.x * 8;
    {
        const float4* xr = (const float4*)(x + (size_t)tok0 * CDIM);
        float4* xd = (float4*)&xs[0][0];
        for (int i = t; i < 8 * CDIM / 4; i += 256) xd[i] = xr[i];
    }
    __syncthreads();
    float acc[8];
    float b = rb1[t];
    #pragma unroll
    for (int k = 0; k < 8; k++) acc[k] = b;
    #pragma unroll 4
    for (int c = 0; c < CDIM; c++) {
        float w = rw1[(size_t)c * HR + t];
        #pragma unroll
        for (int k = 0; k < 8; k++) acc[k] += xs[k][c] * w;
    }
    #pragma unroll
    for (int k = 0; k < 8; k++) hs[k][t] = fmaxf(acc[k], 0.0f);
    __syncthreads();
    int w = t >> 5, l = t & 31;
    float lg = 0.0f;
    if (l < NEXP) {
        lg = rb2[l];
        for (int h = 0; h < HR; h++) lg += hs[w][h] * rw2[(size_t)h * NEXP + l];
    }
    float lgs[NEXP];
    #pragma unroll
    for (int e = 0; e < NEXP; e++) lgs[e] = __shfl_sync(0xffffffffu, lg, e);
    if (l == 0) {
        int n = tok0 + w;
        float mx = lgs[0];
        for (int e = 1; e < NEXP; e++) mx = fmaxf(mx, lgs[e]);
        float ge[NEXP]; float s = 0.0f;
        for (int e = 0; e < NEXP; e++) { ge[e] = expf(lgs[e] - mx); s += ge[e]; }
        for (int e = 0; e < NEXP; e++) ge[e] /= s;
        int i0 = 0;
        for (int e = 1; e < NEXP; e++) if (ge[e] > ge[i0]) i0 = e;
        int i1 = -1;
        for (int e = 0; e < NEXP; e++) {
            if (e == i0) continue;
            if (i1 < 0 || ge[e] > ge[i1]) i1 = e;
        }
        float a = expf(ge[i0] * 0.5f), c = expf(ge[i1] * 0.5f);
        float inv = 1.0f / (a + c);
        g_tok_eidx[n * 2] = i0;  g_tok_eidx[n * 2 + 1] = i1;
        g_tok_w[n * 2] = a * inv;
        g_tok_w[n * 2 + 1] = c * inv;
        atomicAdd(&g_count[i0], 1);
        atomicAdd(&g_count[i1], 1);
    }
}

__global__ void scan_k() {
    if (threadIdx.x == 0) {
        int s = 0;
        for (int e = 0; e < NEXP; e++) { g_base[e] = s; s += g_count[e]; }
    }
}

__global__ void fill_k() {
    int n = blockIdx.x * blockDim.x + threadIdx.x;
    if (n >= NTOK) return;
    #pragma unroll
    for (int k = 0; k < 2; k++) {
        int e = g_tok_eidx[n * 2 + k];
        int slot = atomicAdd(&g_cursor[e], 1);
        int row = g_base[e] + slot;
        g_row_tok[row] = n;
        g_row_of[n * 2 + k] = row;
    }
}

// ---------------- fp32 -> fp16 conversion ------------------------------------
__global__ void f2h_k(const float4* __restrict__ in, uint4* __restrict__ out, int n8) {
    int i = blockIdx.x * blockDim.x + threadIdx.x;
    if (i >= n8) return;
    float4 v0 = in[2 * i], v1 = in[2 * i + 1];
    uint4 o;
    o.x = pkh2(v0.x, v0.y);
    o.y = pkh2(v0.z, v0.w);
    o.z = pkh2(v1.x, v1.y);
    o.w = pkh2(v1.z, v1.w);
    out[i] = o;
}

// ---------------- fp16 mma.sync GEMM, 4 warps, 64x64 warp tiles --------------
template<bool EXPERT, bool GATHER, bool SILU>
__global__ void __launch_bounds__(THREADS, 2) tgemm_k(
    const __half* __restrict__ A, const __half* __restrict__ Bw,
    const float* __restrict__ bias, void* __restrict__ Cm,
    int M, int K, int Nd)
{
    extern __shared__ __half sm[];
    int rowbase = 0;
    if (EXPERT) {
        int e = blockIdx.z;
        M = g_count[e];
        rowbase = g_base[e];
        Bw   += (size_t)e * K * Nd;
        bias += (size_t)e * Nd;
    }
    int m0 = blockIdx.y * BM;
    if (m0 >= M) return;
    int n0 = blockIdx.x * BN;
    int t = threadIdx.x;
    int wid = t >> 5, lane = t & 31;
    int g = lane >> 2, tig = lane & 3;
    int mw = (wid & 1) * 64, nw = (wid >> 1) * 64;
    uint32_t sbase = smem_u32(sm);

    // ---- A cp.async roles: 4 chunks/thread (rows 32 apart)
    int ar = t >> 2, aq = t & 3;
    const __half* aptrs[4];
    uint32_t aoffs[4];
    #pragma unroll
    for (int i = 0; i < 4; i++) {
        int r = ar + 32 * i;
        int rr = m0 + r;
        int rc = rr < M ? rr : (M - 1);
        int src = GATHER ? g_row_tok[rowbase + rc] : (EXPERT ? (rowbase + rc) : rc);
        aptrs[i] = A + (size_t)src * K + aq * 8;
        aoffs[i] = (uint32_t)((r * A_ST + aq * 8) * 2);
    }
    // ---- B cp.async roles: 4 chunks/thread (rows 8 apart)
    int br = t >> 4, bq = t & 15;
    const __half* bptr = Bw + (size_t)br * Nd + n0 + bq * 8;
    uint32_t boff0 = (uint32_t)((br * B_ST + bq * 8) * 2);

    // ---- ldmatrix lane addresses (half units) ----
    uint32_t laneA = (uint32_t)((mw + (lane & 15)) * A_ST + (lane >> 4) * 8);
    uint32_t laneB = (uint32_t)((((lane >> 3) & 1) * 8 + (lane & 7)) * B_ST
                                + nw + ((lane >> 4) & 1) * 8);

    float c[4][8][4];
    #pragma unroll
    for (int mf = 0; mf < 4; mf++)
        #pragma unroll
        for (int nf = 0; nf < 8; nf++)
            #pragma unroll
            for (int i = 0; i < 4; i++) c[mf][nf][i] = 0.0f;

    int iters = K / BK;

    #pragma unroll
    for (int s = 0; s < 2; s++) {
        uint32_t ab = sbase + s * (ABUF * 2);
        uint32_t bb = sbase + (B_BASE + s * BBUF) * 2;
        int kof = s * BK;
        #pragma unroll
        for (int i = 0; i < 4; i++) cp16(ab + aoffs[i], aptrs[i] + kof);
        #pragma unroll
        for (int i = 0; i < 4; i++)
            cp16(bb + boff0 + i * (8 * B_ST * 2), bptr + (size_t)(kof + 8 * i) * Nd);
        cp_commit();
    }

    for (int it = 0; it < iters; it++) {
        cp_wait<1>();
        __syncthreads();
        if (it + 2 < iters) {
            int s = (it + 2) % 3;
            uint32_t ab = sbase + s * (ABUF * 2);
            uint32_t bb = sbase + (B_BASE + s * BBUF) * 2;
            int kof = (it + 2) * BK;
            #pragma unroll
            for (int i = 0; i < 4; i++) cp16(ab + aoffs[i], aptrs[i] + kof);
            #pragma unroll
            for (int i = 0; i < 4; i++)
                cp16(bb + boff0 + i * (8 * B_ST * 2), bptr + (size_t)(kof + 8 * i) * Nd);
        }
        cp_commit();

        uint32_t Ab = sbase + (it % 3) * (ABUF * 2);
        uint32_t Bb = sbase + (B_BASE + (it % 3) * BBUF) * 2;
        #pragma unroll
        for (int ks = 0; ks < 2; ks++) {
            uint32_t a[4][4], b[8][2];
            #pragma unroll
            for (int mf = 0; mf < 4; mf++)
                ldsm4(a[mf], Ab + (laneA + mf * 16 * A_ST + ks * 16) * 2);
            #pragma unroll
            for (int np = 0; np < 4; np++) {
                uint32_t r[4];
                ldsm4t(r, Bb + (laneB + ks * 16 * B_ST + np * 16) * 2);
                b[2 * np][0] = r[0]; b[2 * np][1] = r[1];
                b[2 * np + 1][0] = r[2]; b[2 * np + 1][1] = r[3];
            }
            #pragma unroll
            for (int mf = 0; mf < 4; mf++)
                #pragma unroll
                for (int nf = 0; nf < 8; nf++)
                    mma16(c[mf][nf], a[mf], b[nf]);
        }
        __syncthreads();
    }

    // ---- epilogue ----
    int outbase = EXPERT ? rowbase : 0;
    float2 bv[8];
    #pragma unroll
    for (int nf = 0; nf < 8; nf++)
        bv[nf] = *(const float2*)(bias + n0 + nw + nf * 8 + 2 * tig);
    #pragma unroll
    for (int mf = 0; mf < 4; mf++) {
        int row0 = m0 + mw + mf * 16 + g;
        #pragma unroll
        for (int nf = 0; nf < 8; nf++) {
            int col = n0 + nw + nf * 8 + 2 * tig;
            float v0 = c[mf][nf][0] + bv[nf].x, v1 = c[mf][nf][1] + bv[nf].y;
            float v2 = c[mf][nf][2] + bv[nf].x, v3 = c[mf][nf][3] + bv[nf].y;
            if (SILU) {
                v0 = v0 / (1.0f + __expf(-v0));
                v1 = v1 / (1.0f + __expf(-v1));
                v2 = v2 / (1.0f + __expf(-v2));
                v3 = v3 / (1.0f + __expf(-v3));
                __half* Ch = (__half*)Cm;
                if (row0 < M)
                    *(uint32_t*)(Ch + (size_t)(outbase + row0) * Nd + col) = pkh2(v0, v1);
                if (row0 + 8 < M)
                    *(uint32_t*)(Ch + (size_t)(outbase + row0 + 8) * Nd + col) = pkh2(v2, v3);
            } else {
                float* Cf = (float*)Cm;
                if (row0 < M)
                    *(float2*)(Cf + (size_t)(outbase + row0) * Nd + col) = make_float2(v0, v1);
                if (row0 + 8 < M)
                    *(float2*)(Cf + (size_t)(outbase + row0 + 8) * Nd + col) = make_float2(v2, v3);
            }
        }
    }
}

// ---------------- combine ----------------------------------------------------
__global__ void combine_k(const float* __restrict__ y, float* __restrict__ out) {
    int n = blockIdx.x;
    int r0 = g_row_of[n * 2], r1 = g_row_of[n * 2 + 1];
    float w0 = g_tok_w[n * 2], w1 = g_tok_w[n * 2 + 1];
    const float4* y0 = (const float4*)(y + (size_t)r0 * CDIM);
    const float4* y1 = (const float4*)(y + (size_t)r1 * CDIM);
    float4* o = (float4*)(out + (size_t)n * CDIM);
    for (int c = threadIdx.x; c < CDIM / 4; c += blockDim.x) {
        float4 a = y0[c], b = y1[c], v = o[c];
        v.x += w0 * a.x + w1 * b.x;
        v.y += w0 * a.y + w1 * b.y;
        v.z += w0 * a.z + w1 * b.z;
        v.w += w0 * a.w + w1 * b.w;
        o[c] = v;
    }
}

// ---------------- launch -----------------------------------------------------
extern "C" void kernel_launch(void* const* d_in, const int* in_sizes, int n_in,
                              void* d_out, int out_size) {
    const float* x   = (const float*)d_in[0];
    const float* rw1 = (const float*)d_in[1];
    const float* rb1 = (const float*)d_in[2];
    const float* rw2 = (const float*)d_in[3];
    const float* rb2 = (const float*)d_in[4];
    const float* ew1 = (const float*)d_in[5];
    const float* eb1 = (const float*)d_in[6];
    const float* ew2 = (const float*)d_in[7];
    const float* eb2 = (const float*)d_in[8];
    const float* sw1 = (const float*)d_in[9];
    const float* sb1 = (const float*)d_in[10];
    const float* sw2 = (const float*)d_in[11];
    const float* sb2 = (const float*)d_in[12];
    float* out = (float*)d_out;

    __half *xh, *ew1h, *ew2h, *sw1h, *sw2h, *hbufh, *hsh;
    float *ybuf;
    cudaGetSymbolAddress((void**)&xh,    g_xh);
    cudaGetSymbolAddress((void**)&ew1h,  g_ew1h);
    cudaGetSymbolAddress((void**)&ew2h,  g_ew2h);
    cudaGetSymbolAddress((void**)&sw1h,  g_sw1h);
    cudaGetSymbolAddress((void**)&sw2h,  g_sw2h);
    cudaGetSymbolAddress((void**)&hbufh, g_hbufh);
    cudaGetSymbolAddress((void**)&hsh,   g_hsh);
    cudaGetSymbolAddress((void**)&ybuf,  g_ybuf);

    cudaFuncSetAttribute(tgemm_k<false, false, true>,
                         cudaFuncAttributeMaxDynamicSharedMemorySize, SMEM_BYTES);
    cudaFuncSetAttribute(tgemm_k<false, false, false>,
                         cudaFuncAttributeMaxDynamicSharedMemorySize, SMEM_BYTES);
    cudaFuncSetAttribute(tgemm_k<true, true, true>,
                         cudaFuncAttributeMaxDynamicSharedMemorySize, SMEM_BYTES);
    cudaFuncSetAttribute(tgemm_k<true, false, false>,
                         cudaFuncAttributeMaxDynamicSharedMemorySize, SMEM_BYTES);

    // one-time stream/event setup (host-side only; no device allocation)
    static cudaStream_t s2 = nullptr;
    static cudaEvent_t evFork = nullptr, evW1 = nullptr, evW2 = nullptr, evJoin = nullptr;
    if (!s2) {
        cudaStreamCreateWithFlags(&s2, cudaStreamNonBlocking);
        cudaEventCreateWithFlags(&evFork, cudaEventDisableTiming);
        cudaEventCreateWithFlags(&evW1,   cudaEventDisableTiming);
        cudaEventCreateWithFlags(&evW2,   cudaEventDisableTiming);
        cudaEventCreateWithFlags(&evJoin, cudaEventDisableTiming);
    }

    auto cvt = [&](const float* in, __half* o, size_t n, cudaStream_t st) {
        int n8 = (int)(n / 8);
        f2h_k<<<(n8 + 255) / 256, 256, 0, st>>>((const float4*)in, (uint4*)o, n8);
    };

    // fork s2 off the capture/default stream
    cudaEventRecord(evFork, 0);
    cudaStreamWaitEvent(s2, evFork, 0);

    // s2: conversions then shared-expert chain (independent of routing)
    cvt(x,   xh,   (size_t)NTOK * CDIM, s2);
    cvt(ew1, ew1h, (size_t)NEXP * CDIM * IDIM, s2);
    cudaEventRecord(evW1, s2);
    cvt(sw1, sw1h, (size_t)CDIM * IDIM, s2);
    cvt(ew2, ew2h, (size_t)NEXP * IDIM * CDIM, s2);
    cudaEventRecord(evW2, s2);
    cvt(sw2, sw2h, (size_t)IDIM * CDIM, s2);
    tgemm_k<false, false, true><<<dim3(IDIM / BN, NTOK / BM), THREADS, SMEM_BYTES, s2>>>(
        xh, sw1h, sb1, hsh, NTOK, CDIM, IDIM);
    tgemm_k<false, false, false><<<dim3(CDIM / BN, NTOK / BM), THREADS, SMEM_BYTES, s2>>>(
        hsh, sw2h, sb2, out, NTOK, IDIM, CDIM);
    cudaEventRecord(evJoin, s2);

    // default stream: routing, then expert chain
    init_k<<<1, 32>>>();
    router_k<<<NTOK / 8, 256>>>(x, rw1, rb1, rw2, rb2);
    scan_k<<<1, 32>>>();
    fill_k<<<(NTOK + 255) / 256, 256>>>();

    cudaStreamWaitEvent(0, evW1, 0);
    tgemm_k<true, true, true><<<dim3(IDIM / BN, NTOK / BM, NEXP), THREADS, SMEM_BYTES>>>(
        xh, ew1h, eb1, hbufh, 0, CDIM, IDIM);
    cudaStreamWaitEvent(0, evW2, 0);
    tgemm_k<true, false, false><<<dim3(CDIM / BN, NTOK / BM, NEXP), THREADS, SMEM_BYTES>>>(
        hbufh, ew2h, eb2, ybuf, 0, IDIM, CDIM);

    // join shared chain, then combine (out += expert mix)
    cudaStreamWaitEvent(0, evJoin, 0);
    combine_k<<<NTOK, 256>>>(ybuf, out);
}